// round 6
// baseline (speedup 1.0000x reference)
#include <cuda_runtime.h>

#define TT     16
#define BB     32
#define IDIM   512
#define HDIM   1024
#define DECAYF 0.999f

#define NBLK   128
#define NTHR   256

#define WPAD   12                       // floats per k-row (48B, 16B-aligned)
#define WSZ    (HDIM*WPAD)              // 12288 floats per weight slice
#define ASZ    (256*32)                 // 8192 floats per A chunk buffer
#define SMEM_TOTAL ((3*WSZ + 2*ASZ)*4)  // 212992 bytes

// ---------------- scratch (device globals; no allocations) ----------------
__device__ __align__(16) float g_R[TT*BB*IDIM];      // x_s @ inpt_mat
__device__ __align__(16) float g_D[TT*TT*BB];        // D[t][s][b]
__device__ __align__(16) float g_ybase[TT*BB*HDIM];  // x@main^T + bias
__device__ __align__(16) float g_L[TT*BB*HDIM];      // left history
__device__ __align__(16) float g_h[BB*HDIM];         // relu hidden
__device__ __align__(16) float g_y[BB*HDIM];         // current y
__device__ unsigned g_cnt;
__device__ volatile unsigned g_gen;

// ---------------- packed fp32x2 helpers ------------------------------------
__device__ __forceinline__ void ffma2(unsigned long long &d, unsigned long long a,
                                      unsigned long long b)
{
    asm("fma.rn.f32x2 %0, %1, %2, %0;" : "+l"(d) : "l"(a), "l"(b));
}
__device__ __forceinline__ unsigned long long rep2(float x)
{
    unsigned long long r;
    asm("mov.b64 %0, {%1, %1};" : "=l"(r) : "f"(x));
    return r;
}

// ---------------- software grid barrier ------------------------------------
__device__ __forceinline__ void gridbar()
{
    __syncthreads();
    if (threadIdx.x == 0) {
        unsigned gen = g_gen;
        __threadfence();
        unsigned old = atomicAdd(&g_cnt, 1u);
        if (old == NBLK - 1u) {
            g_cnt = 0u;
            __threadfence();
            g_gen = gen + 1u;
            __threadfence();
        } else {
            while (g_gen == gen) { __nanosleep(32); }
            __threadfence();
        }
    }
    __syncthreads();
}

// ---------------------------------------------------------------------------
// precompute kernels
// ---------------------------------------------------------------------------
#define FMA16() \
    acc[0][0] += a.x*b.x; acc[0][1] += a.x*b.y; acc[0][2] += a.x*b.z; acc[0][3] += a.x*b.w; \
    acc[1][0] += a.y*b.x; acc[1][1] += a.y*b.y; acc[1][2] += a.y*b.z; acc[1][3] += a.y*b.w; \
    acc[2][0] += a.z*b.x; acc[2][1] += a.z*b.y; acc[2][2] += a.z*b.z; acc[2][3] += a.z*b.w; \
    acc[3][0] += a.w*b.x; acc[3][1] += a.w*b.y; acc[3][2] += a.w*b.z; acc[3][3] += a.w*b.w;

__global__ void kR(const float* __restrict__ X, const float* __restrict__ Bm)
{
    const int K = IDIM, N = IDIM;
    int mtile = blockIdx.x, ntile = blockIdx.y;
    int tid = threadIdx.x;
    __shared__ __align__(16) float As[32*36];
    __shared__ __align__(16) float Bs[32*68];
    float acc[4][4] = {};
    int tx = tid & 15, ty = tid >> 4;
    int m0 = ty*4, n0 = tx*4;
    for (int kb = 0; kb < K; kb += 32) {
        int k4 = tid & 7;
        int mrow = tid >> 3;
        #pragma unroll
        for (int r = 0; r < 2; r++) {
            int mm = mrow + r*16;
            float4 v = *(const float4*)(X + (mtile*32+mm)*K + kb + k4*4);
            As[(k4*4+0)*36+mm] = v.x;
            As[(k4*4+1)*36+mm] = v.y;
            As[(k4*4+2)*36+mm] = v.z;
            As[(k4*4+3)*36+mm] = v.w;
        }
        int n4 = tid & 15, kq = tid >> 4;
        #pragma unroll
        for (int r = 0; r < 4; r++) {
            int k = kq + r*8;
            float4 v = *(const float4*)(Bm + (kb+k)*N + ntile*64 + n4*4);
            *(float4*)&Bs[k*68 + n4*4] = v;
        }
        __syncthreads();
        #pragma unroll
        for (int kk = 0; kk < 32; kk++) {
            float4 a = *(const float4*)(As + kk*36 + m0);
            float4 b = *(const float4*)(Bs + kk*68 + n0);
            FMA16()
        }
        __syncthreads();
    }
    #pragma unroll
    for (int i = 0; i < 4; i++)
        *(float4*)&g_R[(mtile*32+m0+i)*N + ntile*64 + n0] =
            make_float4(acc[i][0], acc[i][1], acc[i][2], acc[i][3]);
}

__global__ void kYbase(const float* __restrict__ X, const float* __restrict__ W,
                       const float* __restrict__ bias)
{
    const int K = IDIM, N = HDIM;
    int ntile = blockIdx.x, mtile = blockIdx.y;
    int tid = threadIdx.x;
    __shared__ __align__(16) float As[32*68];
    __shared__ __align__(16) float Bs[32*68];
    float acc[4][4] = {};
    int tx = tid & 15, ty = tid >> 4;
    int m0 = ty*4, n0 = tx*4;
    for (int kb = 0; kb < K; kb += 32) {
        int k4 = tid & 7;
        int row = tid >> 3;
        #pragma unroll
        for (int r = 0; r < 2; r++) {
            int mm = row + r*32;
            float4 v = *(const float4*)(X + (mtile*64+mm)*K + kb + k4*4);
            As[(k4*4+0)*68+mm] = v.x;
            As[(k4*4+1)*68+mm] = v.y;
            As[(k4*4+2)*68+mm] = v.z;
            As[(k4*4+3)*68+mm] = v.w;
        }
        #pragma unroll
        for (int r = 0; r < 2; r++) {
            int nn = row + r*32;
            float4 v = *(const float4*)(W + (ntile*64+nn)*K + kb + k4*4);
            Bs[(k4*4+0)*68+nn] = v.x;
            Bs[(k4*4+1)*68+nn] = v.y;
            Bs[(k4*4+2)*68+nn] = v.z;
            Bs[(k4*4+3)*68+nn] = v.w;
        }
        __syncthreads();
        #pragma unroll
        for (int kk = 0; kk < 32; kk++) {
            float4 a = *(const float4*)(As + kk*68 + m0);
            float4 b = *(const float4*)(Bs + kk*68 + n0);
            FMA16()
        }
        __syncthreads();
    }
    #pragma unroll
    for (int i = 0; i < 4; i++) {
        int grow = mtile*64 + m0 + i;
        int col0 = ntile*64 + n0;
        float4 v = make_float4(acc[i][0] + bias[col0+0],
                               acc[i][1] + bias[col0+1],
                               acc[i][2] + bias[col0+2],
                               acc[i][3] + bias[col0+3]);
        *(float4*)&g_ybase[grow*N + col0] = v;
        if (grow < BB) *(float4*)&g_y[grow*N + col0] = v;   // t=0 seed
    }
}

__global__ void kD(const float* __restrict__ X)
{
    int t = blockIdx.x, s = blockIdx.y;
    if (s >= t) return;
    int w = threadIdx.x >> 5, lane = threadIdx.x & 31;
    for (int b = w; b < BB; b += 8) {
        const float* xb = X + (t*BB + b)*IDIM;
        const float* rb = g_R + (s*BB + b)*IDIM;
        float sum = 0.f;
        for (int i = lane; i < IDIM; i += 32) sum += xb[i]*rb[i];
        #pragma unroll
        for (int o = 16; o > 0; o >>= 1) sum += __shfl_down_sync(0xffffffffu, sum, o);
        if (lane == 0) g_D[(t*TT + s)*BB + b] = sum;
    }
}

// ---------------------------------------------------------------------------
// one GEMM phase: C[32, n0:n0+8] = A[32,1024] @ Wrows^T, full K per block,
// fused epilogue. Block owns its tile; no cross-block reduction.
// ---------------------------------------------------------------------------
__device__ __forceinline__ void gemm_phase(
    const float* __restrict__ Ag,   // A operand in global [32,1024]
    const float* Ws,                // smem weight rows (this phase), [k][WPAD]
    float* As,                      // smem A double buffer (2*ASZ floats)
    int j, int t,
    const float* __restrict__ b1, const float* __restrict__ b2,
    float* __restrict__ out)
{
    int tid = threadIdx.x;
    int mp = tid & 15, ks = tid >> 4;      // m-pair 0..15, k-slice 0..15
    int n0 = blockIdx.x * 8;

    unsigned long long acc[2][4];
    #pragma unroll
    for (int mi = 0; mi < 2; mi++)
        #pragma unroll
        for (int np = 0; np < 4; np++) acc[mi][np] = 0ull;

    int lm = tid & 31, cq = tid >> 5;      // staging: m row 0..31, k-octet 0..7
    float4 st[8];

    // prologue: chunk 0 -> buf 0
    #pragma unroll
    for (int r = 0; r < 8; r++)
        st[r] = __ldcg((const float4*)(Ag + lm*HDIM + cq*32 + r*4));
    #pragma unroll
    for (int r = 0; r < 8; r++) {
        int k = cq*32 + r*4;
        As[(k+0)*32+lm] = st[r].x; As[(k+1)*32+lm] = st[r].y;
        As[(k+2)*32+lm] = st[r].z; As[(k+3)*32+lm] = st[r].w;
    }
    __syncthreads();

    #pragma unroll 1
    for (int c = 0; c < 4; c++) {
        if (c < 3) {
            #pragma unroll
            for (int r = 0; r < 8; r++)
                st[r] = __ldcg((const float4*)(Ag + lm*HDIM + (c+1)*256 + cq*32 + r*4));
        }
        const float* Ab = As + (c & 1)*ASZ;
        const float* Wk = Ws + (c*256)*WPAD;
        #pragma unroll
        for (int i = 0; i < 16; i++) {
            int kl = ks*16 + i;
            union { unsigned long long u; float2 f; } ap;
            ap.u = *(const unsigned long long*)&Ab[kl*32 + mp*2];
            unsigned long long am0 = rep2(ap.f.x);
            unsigned long long am1 = rep2(ap.f.y);
            union { float4 f; unsigned long long u[2]; } w0, w1;
            w0.f = *(const float4*)&Wk[kl*WPAD + 0];
            w1.f = *(const float4*)&Wk[kl*WPAD + 4];
            ffma2(acc[0][0], am0, w0.u[0]); ffma2(acc[0][1], am0, w0.u[1]);
            ffma2(acc[0][2], am0, w1.u[0]); ffma2(acc[0][3], am0, w1.u[1]);
            ffma2(acc[1][0], am1, w0.u[0]); ffma2(acc[1][1], am1, w0.u[1]);
            ffma2(acc[1][2], am1, w1.u[0]); ffma2(acc[1][3], am1, w1.u[1]);
        }
        if (c < 3) {
            float* Ad = As + ((c+1) & 1)*ASZ;
            #pragma unroll
            for (int r = 0; r < 8; r++) {
                int k = cq*32 + r*4;
                Ad[(k+0)*32+lm] = st[r].x; Ad[(k+1)*32+lm] = st[r].y;
                Ad[(k+2)*32+lm] = st[r].z; Ad[(k+3)*32+lm] = st[r].w;
            }
        }
        __syncthreads();
    }

    // in-block reduction over 16 k-slices (reuse As buf0 region)
    float* red = As;
    union { unsigned long long u[2]; float4 f; } p;
    p.u[0] = acc[0][0]; p.u[1] = acc[0][1]; *(float4*)&red[tid*16 +  0] = p.f;
    p.u[0] = acc[0][2]; p.u[1] = acc[0][3]; *(float4*)&red[tid*16 +  4] = p.f;
    p.u[0] = acc[1][0]; p.u[1] = acc[1][1]; *(float4*)&red[tid*16 +  8] = p.f;
    p.u[0] = acc[1][2]; p.u[1] = acc[1][3]; *(float4*)&red[tid*16 + 12] = p.f;
    __syncthreads();

    int m = tid >> 3, n = tid & 7;
    float s = 0.f;
    #pragma unroll
    for (int q = 0; q < 16; q++) s += red[q*256 + m*8 + n];

    int col = n0 + n;
    if (j == 0) {
        g_h[m*HDIM + col] = fmaxf(s + __ldg(&b1[col]), 0.f);
    } else if (j == 1) {
        out[(t*BB + m)*HDIM + col] = s + __ldg(&b2[col]);
    } else {
        g_L[(t*BB + m)*HDIM + col] = s;
        if (t < TT-1) {
            float y = __ldcg(&g_ybase[((t+1)*BB + m)*HDIM + col]);
            float dp = 1.f;
            for (int s2 = t; s2 >= 0; s2--) {
                float lv = (s2 == t) ? s : __ldcg(&g_L[(s2*BB + m)*HDIM + col]);
                y += dp * __ldcg(&g_D[((t+1)*TT + s2)*BB + m]) * lv;
                dp *= DECAYF;
            }
            g_y[m*HDIM + col] = y;
        }
    }
}

// ---------------------------------------------------------------------------
__global__ void __launch_bounds__(NTHR, 1)
stp_persist(const float* __restrict__ W1, const float* __restrict__ b1,
            const float* __restrict__ W2, const float* __restrict__ b2,
            const float* __restrict__ hidW, float* __restrict__ out)
{
    extern __shared__ float sm[];
    float* Ws = sm;                  // [3][WSZ]
    float* As = sm + 3*WSZ;          // [2][ASZ]
    int tid = threadIdx.x;
    int n0 = blockIdx.x * 8;

    // load this block's 8 rows of each weight into smem, [k][n] with WPAD
    {
        const float* Wsrc[3] = { W1, W2, hidW };
        int wn = tid & 7, kq = tid >> 3;   // n 0..7, kq 0..31
        for (int w = 0; w < 3; w++) {
            const float* src = Wsrc[w] + (n0 + wn)*HDIM;
            float* dst = Ws + w*WSZ;
            #pragma unroll
            for (int r = 0; r < 8; r++) {
                int k4 = r*128 + kq*4;
                float4 v = __ldg((const float4*)(src + k4));
                dst[(k4+0)*WPAD + wn] = v.x;
                dst[(k4+1)*WPAD + wn] = v.y;
                dst[(k4+2)*WPAD + wn] = v.z;
                dst[(k4+3)*WPAD + wn] = v.w;
            }
        }
    }
    __syncthreads();

    #pragma unroll 1
    for (int t = 0; t < TT; t++) {
        gemm_phase(g_y, Ws,         As, 0, t, b1, b2, out);
        gridbar();
        gemm_phase(g_h, Ws + WSZ,   As, 1, t, b1, b2, out);
        if (t < TT-1) {
            gridbar();
            gemm_phase(out + t*BB*HDIM, Ws + 2*WSZ, As, 2, t, b1, b2, out);
            gridbar();
        }
    }
}

// ---------------------------------------------------------------------------
extern "C" void kernel_launch(void* const* d_in, const int* in_sizes, int n_in,
                              void* d_out, int out_size)
{
    (void)in_sizes; (void)n_in; (void)out_size;
    const float* x     = (const float*)d_in[0];
    const float* inpt  = (const float*)d_in[1];
    const float* hid   = (const float*)d_in[2];
    const float* mainW = (const float*)d_in[3];
    const float* mainb = (const float*)d_in[4];
    const float* W1    = (const float*)d_in[5];
    const float* b1    = (const float*)d_in[6];
    const float* W2    = (const float*)d_in[7];
    const float* b2    = (const float*)d_in[8];
    float* out = (float*)d_out;

    // not a stream op; safe under graph capture, called unconditionally
    cudaFuncSetAttribute(stp_persist,
                         cudaFuncAttributeMaxDynamicSharedMemorySize,
                         SMEM_TOTAL);

    kR     <<<dim3(16, 8),  128>>>(x, inpt);
    kYbase <<<dim3(16, 8),  256>>>(x, mainW, mainb);
    kD     <<<dim3(16, 16), 256>>>(x);
    stp_persist<<<NBLK, NTHR, SMEM_TOTAL>>>(W1, b1, W2, b2, hid, out);
}